// round 1
// baseline (speedup 1.0000x reference)
#include <cuda_runtime.h>
#include <math.h>

// Problem constants
#define MB    8
#define NQ    1024
#define NKV   1024
#define DXD   512
#define HH    8
#define HDD   64
#define INNER 512
#define KHID  16
#define SCALE 0.125f   // 1/sqrt(64)

// Scratch (device globals — no allocation allowed)
__device__ float g_q  [MB * NQ  * INNER];
__device__ float g_k  [MB * NKV * INNER];
__device__ float g_v  [MB * NKV * INNER];
__device__ float g_ctx[MB * NQ  * INNER];

// ---------------------------------------------------------------------------
// SGEMM: C[M,N] = A[M,K] @ B[K,N] (+ bias). Row-major. 128x128 tile, BK=8,
// 256 threads, 8x8 micro-tile per thread. All dims divisible (8192/512/512).
// ---------------------------------------------------------------------------
__global__ void __launch_bounds__(256) sgemm128(
    const float* __restrict__ A, const float* __restrict__ B,
    const float* __restrict__ bias, float* __restrict__ C,
    int Mtot, int N, int K)
{
    __shared__ float As[8][128];   // transposed A tile: As[k][m]
    __shared__ float Bs[8][128];

    const int tid  = threadIdx.x;
    const int bm   = blockIdx.y * 128;
    const int bn   = blockIdx.x * 128;
    const int arow = tid >> 1;
    const int acol = (tid & 1) * 4;
    const int brow = tid >> 5;
    const int bcol = (tid & 31) * 4;
    const int ty   = tid >> 4;
    const int tx   = tid & 15;

    float acc[8][8];
#pragma unroll
    for (int i = 0; i < 8; i++)
#pragma unroll
        for (int j = 0; j < 8; j++) acc[i][j] = 0.f;

    for (int k0 = 0; k0 < K; k0 += 8) {
        float4 a = *(const float4*)(A + (size_t)(bm + arow) * K + k0 + acol);
        As[acol + 0][arow] = a.x;
        As[acol + 1][arow] = a.y;
        As[acol + 2][arow] = a.z;
        As[acol + 3][arow] = a.w;
        *(float4*)&Bs[brow][bcol] =
            *(const float4*)(B + (size_t)(k0 + brow) * N + bn + bcol);
        __syncthreads();

#pragma unroll
        for (int kk = 0; kk < 8; kk++) {
            float4 a0 = *(float4*)&As[kk][ty * 8];
            float4 a1 = *(float4*)&As[kk][ty * 8 + 4];
            float4 b0 = *(float4*)&Bs[kk][tx * 8];
            float4 b1 = *(float4*)&Bs[kk][tx * 8 + 4];
            float ar[8] = {a0.x, a0.y, a0.z, a0.w, a1.x, a1.y, a1.z, a1.w};
            float br[8] = {b0.x, b0.y, b0.z, b0.w, b1.x, b1.y, b1.z, b1.w};
#pragma unroll
            for (int i = 0; i < 8; i++)
#pragma unroll
                for (int j = 0; j < 8; j++) acc[i][j] += ar[i] * br[j];
        }
        __syncthreads();
    }

#pragma unroll
    for (int i = 0; i < 8; i++) {
        size_t row = (size_t)(bm + ty * 8 + i);
        float* crow = C + row * N + bn + tx * 8;
#pragma unroll
        for (int j4 = 0; j4 < 2; j4++) {
            float4 o = make_float4(acc[i][j4 * 4 + 0], acc[i][j4 * 4 + 1],
                                   acc[i][j4 * 4 + 2], acc[i][j4 * 4 + 3]);
            if (bias) {
                const float* bp = bias + bn + tx * 8 + j4 * 4;
                o.x += bp[0]; o.y += bp[1]; o.z += bp[2]; o.w += bp[3];
            }
            *(float4*)(crow + j4 * 4) = o;
        }
    }
}

// ---------------------------------------------------------------------------
// Fused attention: per-CTA (m, h, 128-query tile). Online softmax over keys,
// factored kernel-MLP bias:
//   bias(q,k,h) = kb2[h] + sum_j relu(uq[j] - vk[j]) * kw2[j,h]
//   uq[j] = tq0*kw1[0,j] + tq1*kw1[1,j] + kb1[j]   (per-thread regs)
//   vk[j] = tk0*kw1[0,j] + tk1*kw1[1,j]            (smem per key tile)
// ---------------------------------------------------------------------------
#define BQ 128
#define BK 64
#define ATTN_SMEM (BK*16*16*2 + BK*16*4 + BQ*68*4)   // Ks + Vs + Hk + Qs = 71680B

__global__ void __launch_bounds__(BQ) attn_kernel(
    const float* __restrict__ Qg, const float* __restrict__ Kg,
    const float* __restrict__ Vg,
    const float* __restrict__ Tq, const float* __restrict__ Tk,
    const float* __restrict__ kw1, const float* __restrict__ kb1,
    const float* __restrict__ kw2, const float* __restrict__ kb2,
    float* __restrict__ ctx)
{
    extern __shared__ float smemf[];
    float4* Ks = (float4*)smemf;          // BK*16 float4
    float4* Vs = Ks + BK * 16;            // BK*16 float4
    float*  Hk = (float*)(Vs + BK * 16);  // BK*16 floats
    float*  Qs = Hk + BK * 16;            // BQ rows, stride 68 floats (pad vs bank conflicts)

    const int m   = blockIdx.z;
    const int h   = blockIdx.y;
    const int q0  = blockIdx.x * BQ;
    const int tid = threadIdx.x;

    // Load Q tile (pre-scaled)
    for (int i = tid; i < BQ * 16; i += BQ) {
        int r = i >> 4, c = i & 15;
        float4 v = *(const float4*)(Qg + ((size_t)(m * NQ + q0 + r)) * INNER + h * HDD + c * 4);
        *(float4*)(Qs + r * 68 + c * 4) =
            make_float4(v.x * SCALE, v.y * SCALE, v.z * SCALE, v.w * SCALE);
    }

    const int q = q0 + tid;
    const float tq0 = Tq[((size_t)m * NQ + q) * 2 + 0];
    const float tq1 = Tq[((size_t)m * NQ + q) * 2 + 1];
    float uq[KHID], w2c[KHID];
#pragma unroll
    for (int j = 0; j < KHID; j++) {
        uq[j]  = tq0 * kw1[j] + tq1 * kw1[KHID + j] + kb1[j];
        w2c[j] = kw2[j * HH + h];
    }
    const float bconst = kb2[h];

    float mmax = -1e30f, lsum = 0.f;
    float4 acc[16];
#pragma unroll
    for (int c = 0; c < 16; c++) acc[c] = make_float4(0.f, 0.f, 0.f, 0.f);

    const float* qrow = Qs + tid * 68;

    for (int k0 = 0; k0 < NKV; k0 += BK) {
        __syncthreads();
        for (int i = tid; i < BK * 16; i += BQ) {
            int r = i >> 4, c = i & 15;
            size_t off = ((size_t)(m * NKV + k0 + r)) * INNER + h * HDD + c * 4;
            Ks[i] = *(const float4*)(Kg + off);
            Vs[i] = *(const float4*)(Vg + off);
        }
        for (int i = tid; i < BK * KHID; i += BQ) {
            int r = i >> 4, j = i & 15;
            float t0 = Tk[((size_t)m * NKV + k0 + r) * 2 + 0];
            float t1 = Tk[((size_t)m * NKV + k0 + r) * 2 + 1];
            Hk[i] = t0 * kw1[j] + t1 * kw1[KHID + j];
        }
        __syncthreads();

        for (int kk = 0; kk < BK; kk++) {
            const float4* kr = Ks + kk * 16;
            float s = bconst;
#pragma unroll
            for (int c = 0; c < 16; c++) {
                float4 qv = *(const float4*)(qrow + c * 4);
                float4 kv = kr[c];
                s += qv.x * kv.x + qv.y * kv.y + qv.z * kv.z + qv.w * kv.w;
            }
            const float4* hk4 = (const float4*)(Hk + kk * 16);
#pragma unroll
            for (int c = 0; c < 4; c++) {
                float4 hv = hk4[c];
                s += fmaxf(uq[c * 4 + 0] - hv.x, 0.f) * w2c[c * 4 + 0];
                s += fmaxf(uq[c * 4 + 1] - hv.y, 0.f) * w2c[c * 4 + 1];
                s += fmaxf(uq[c * 4 + 2] - hv.z, 0.f) * w2c[c * 4 + 2];
                s += fmaxf(uq[c * 4 + 3] - hv.w, 0.f) * w2c[c * 4 + 3];
            }
            if (s > mmax) {   // rare after warmup: rescale running state
                float corr = __expf(mmax - s);
                lsum *= corr;
#pragma unroll
                for (int c = 0; c < 16; c++) {
                    acc[c].x *= corr; acc[c].y *= corr;
                    acc[c].z *= corr; acc[c].w *= corr;
                }
                mmax = s;
            }
            float p = __expf(s - mmax);
            lsum += p;
            const float4* vr = Vs + kk * 16;
#pragma unroll
            for (int c = 0; c < 16; c++) {
                float4 vv = vr[c];
                acc[c].x += p * vv.x; acc[c].y += p * vv.y;
                acc[c].z += p * vv.z; acc[c].w += p * vv.w;
            }
        }
    }

    const float inv = 1.f / lsum;
    float* orow = ctx + ((size_t)(m * NQ + q)) * INNER + h * HDD;
#pragma unroll
    for (int c = 0; c < 16; c++) {
        *(float4*)(orow + c * 4) = make_float4(acc[c].x * inv, acc[c].y * inv,
                                               acc[c].z * inv, acc[c].w * inv);
    }
}

// ---------------------------------------------------------------------------
extern "C" void kernel_launch(void* const* d_in, const int* in_sizes, int n_in,
                              void* d_out, int out_size)
{
    const float* xq    = (const float*)d_in[0];
    const float* xk    = (const float*)d_in[1];
    const float* xv    = (const float*)d_in[2];
    const float* tq    = (const float*)d_in[3];
    const float* tk    = (const float*)d_in[4];
    const float* w_q   = (const float*)d_in[5];
    const float* w_k   = (const float*)d_in[6];
    const float* w_v   = (const float*)d_in[7];
    const float* w_out = (const float*)d_in[8];
    const float* b_out = (const float*)d_in[9];
    const float* kw1   = (const float*)d_in[10];
    const float* kb1   = (const float*)d_in[11];
    const float* kw2   = (const float*)d_in[12];
    const float* kb2   = (const float*)d_in[13];
    float* out = (float*)d_out;

    float *qp, *kp, *vp, *cp;
    cudaGetSymbolAddress((void**)&qp, g_q);
    cudaGetSymbolAddress((void**)&kp, g_k);
    cudaGetSymbolAddress((void**)&vp, g_v);
    cudaGetSymbolAddress((void**)&cp, g_ctx);

    cudaFuncSetAttribute(attn_kernel,
                         cudaFuncAttributeMaxDynamicSharedMemorySize, ATTN_SMEM);

    const int Mtot = MB * NQ;                 // 8192
    dim3 gg(INNER / 128, Mtot / 128);         // (4, 64)
    sgemm128<<<gg, 256>>>(xq, w_q, nullptr, qp, Mtot, INNER, DXD);
    sgemm128<<<gg, 256>>>(xk, w_k, nullptr, kp, Mtot, INNER, DXD);
    sgemm128<<<gg, 256>>>(xv, w_v, nullptr, vp, Mtot, INNER, DXD);

    dim3 ga(NQ / BQ, HH, MB);                 // (8, 8, 8)
    attn_kernel<<<ga, BQ, ATTN_SMEM>>>(qp, kp, vp, tq, tk,
                                       kw1, kb1, kw2, kb2, cp);

    dim3 go(DXD / 128, Mtot / 128);           // (4, 64)
    sgemm128<<<go, 256>>>(cp, w_out, b_out, out, Mtot, DXD, INNER);
}

// round 2
// speedup vs baseline: 1.0003x; 1.0003x over previous
#include <cuda_runtime.h>
#include <math.h>

// Problem constants
#define MB    8
#define NQ    1024
#define NKV   1024
#define DXD   512
#define HH    8
#define HDD   64
#define INNER 512
#define KHID  16
#define SCALE 0.125f   // 1/sqrt(64)

// Scratch (device globals — no allocation allowed)
__device__ float g_q  [MB * NQ  * INNER];
__device__ float g_k  [MB * NKV * INNER];
__device__ float g_v  [MB * NKV * INNER];
__device__ float g_ctx[MB * NQ  * INNER];

// ---------------------------------------------------------------------------
// SGEMM: C[M,N] = A[M,K] @ B[K,N] (+ bias). Row-major. 128x128 tile, BK=8,
// 256 threads, 8x8 micro-tile per thread. All dims divisible (8192/512/512).
// ---------------------------------------------------------------------------
__global__ void __launch_bounds__(256) sgemm128(
    const float* __restrict__ A, const float* __restrict__ B,
    const float* __restrict__ bias, float* __restrict__ C,
    int Mtot, int N, int K)
{
    __shared__ float As[8][128];   // transposed A tile: As[k][m]
    __shared__ float Bs[8][128];

    const int tid  = threadIdx.x;
    const int bm   = blockIdx.y * 128;
    const int bn   = blockIdx.x * 128;
    const int arow = tid >> 1;
    const int acol = (tid & 1) * 4;
    const int brow = tid >> 5;
    const int bcol = (tid & 31) * 4;
    const int ty   = tid >> 4;
    const int tx   = tid & 15;

    float acc[8][8];
#pragma unroll
    for (int i = 0; i < 8; i++)
#pragma unroll
        for (int j = 0; j < 8; j++) acc[i][j] = 0.f;

    for (int k0 = 0; k0 < K; k0 += 8) {
        float4 a = *(const float4*)(A + (size_t)(bm + arow) * K + k0 + acol);
        As[acol + 0][arow] = a.x;
        As[acol + 1][arow] = a.y;
        As[acol + 2][arow] = a.z;
        As[acol + 3][arow] = a.w;
        *(float4*)&Bs[brow][bcol] =
            *(const float4*)(B + (size_t)(k0 + brow) * N + bn + bcol);
        __syncthreads();

#pragma unroll
        for (int kk = 0; kk < 8; kk++) {
            float4 a0 = *(float4*)&As[kk][ty * 8];
            float4 a1 = *(float4*)&As[kk][ty * 8 + 4];
            float4 b0 = *(float4*)&Bs[kk][tx * 8];
            float4 b1 = *(float4*)&Bs[kk][tx * 8 + 4];
            float ar[8] = {a0.x, a0.y, a0.z, a0.w, a1.x, a1.y, a1.z, a1.w};
            float br[8] = {b0.x, b0.y, b0.z, b0.w, b1.x, b1.y, b1.z, b1.w};
#pragma unroll
            for (int i = 0; i < 8; i++)
#pragma unroll
                for (int j = 0; j < 8; j++) acc[i][j] += ar[i] * br[j];
        }
        __syncthreads();
    }

#pragma unroll
    for (int i = 0; i < 8; i++) {
        size_t row = (size_t)(bm + ty * 8 + i);
        float* crow = C + row * N + bn + tx * 8;
#pragma unroll
        for (int j4 = 0; j4 < 2; j4++) {
            float4 o = make_float4(acc[i][j4 * 4 + 0], acc[i][j4 * 4 + 1],
                                   acc[i][j4 * 4 + 2], acc[i][j4 * 4 + 3]);
            if (bias) {
                const float* bp = bias + bn + tx * 8 + j4 * 4;
                o.x += bp[0]; o.y += bp[1]; o.z += bp[2]; o.w += bp[3];
            }
            *(float4*)(crow + j4 * 4) = o;
        }
    }
}

// ---------------------------------------------------------------------------
// Fused attention: per-CTA (m, h, 128-query tile). Online softmax over keys,
// factored kernel-MLP bias:
//   bias(q,k,h) = kb2[h] + sum_j relu(uq[j] - vk[j]) * kw2[j,h]
//   uq[j] = tq0*kw1[0,j] + tq1*kw1[1,j] + kb1[j]   (per-thread regs)
//   vk[j] = tk0*kw1[0,j] + tk1*kw1[1,j]            (smem per key tile)
// ---------------------------------------------------------------------------
#define BQ 128
#define BK 64
#define ATTN_SMEM (BK*16*16*2 + BK*16*4 + BQ*68*4)   // Ks + Vs + Hk + Qs = 71680B

__global__ void __launch_bounds__(BQ) attn_kernel(
    const float* __restrict__ Qg, const float* __restrict__ Kg,
    const float* __restrict__ Vg,
    const float* __restrict__ Tq, const float* __restrict__ Tk,
    const float* __restrict__ kw1, const float* __restrict__ kb1,
    const float* __restrict__ kw2, const float* __restrict__ kb2,
    float* __restrict__ ctx)
{
    extern __shared__ float smemf[];
    float4* Ks = (float4*)smemf;          // BK*16 float4
    float4* Vs = Ks + BK * 16;            // BK*16 float4
    float*  Hk = (float*)(Vs + BK * 16);  // BK*16 floats
    float*  Qs = Hk + BK * 16;            // BQ rows, stride 68 floats (pad vs bank conflicts)

    const int m   = blockIdx.z;
    const int h   = blockIdx.y;
    const int q0  = blockIdx.x * BQ;
    const int tid = threadIdx.x;

    // Load Q tile (pre-scaled)
    for (int i = tid; i < BQ * 16; i += BQ) {
        int r = i >> 4, c = i & 15;
        float4 v = *(const float4*)(Qg + ((size_t)(m * NQ + q0 + r)) * INNER + h * HDD + c * 4);
        *(float4*)(Qs + r * 68 + c * 4) =
            make_float4(v.x * SCALE, v.y * SCALE, v.z * SCALE, v.w * SCALE);
    }

    const int q = q0 + tid;
    const float tq0 = Tq[((size_t)m * NQ + q) * 2 + 0];
    const float tq1 = Tq[((size_t)m * NQ + q) * 2 + 1];
    float uq[KHID], w2c[KHID];
#pragma unroll
    for (int j = 0; j < KHID; j++) {
        uq[j]  = tq0 * kw1[j] + tq1 * kw1[KHID + j] + kb1[j];
        w2c[j] = kw2[j * HH + h];
    }
    const float bconst = kb2[h];

    float mmax = -1e30f, lsum = 0.f;
    float4 acc[16];
#pragma unroll
    for (int c = 0; c < 16; c++) acc[c] = make_float4(0.f, 0.f, 0.f, 0.f);

    const float* qrow = Qs + tid * 68;

    for (int k0 = 0; k0 < NKV; k0 += BK) {
        __syncthreads();
        for (int i = tid; i < BK * 16; i += BQ) {
            int r = i >> 4, c = i & 15;
            size_t off = ((size_t)(m * NKV + k0 + r)) * INNER + h * HDD + c * 4;
            Ks[i] = *(const float4*)(Kg + off);
            Vs[i] = *(const float4*)(Vg + off);
        }
        for (int i = tid; i < BK * KHID; i += BQ) {
            int r = i >> 4, j = i & 15;
            float t0 = Tk[((size_t)m * NKV + k0 + r) * 2 + 0];
            float t1 = Tk[((size_t)m * NKV + k0 + r) * 2 + 1];
            Hk[i] = t0 * kw1[j] + t1 * kw1[KHID + j];
        }
        __syncthreads();

        for (int kk = 0; kk < BK; kk++) {
            const float4* kr = Ks + kk * 16;
            float s = bconst;
#pragma unroll
            for (int c = 0; c < 16; c++) {
                float4 qv = *(const float4*)(qrow + c * 4);
                float4 kv = kr[c];
                s += qv.x * kv.x + qv.y * kv.y + qv.z * kv.z + qv.w * kv.w;
            }
            const float4* hk4 = (const float4*)(Hk + kk * 16);
#pragma unroll
            for (int c = 0; c < 4; c++) {
                float4 hv = hk4[c];
                s += fmaxf(uq[c * 4 + 0] - hv.x, 0.f) * w2c[c * 4 + 0];
                s += fmaxf(uq[c * 4 + 1] - hv.y, 0.f) * w2c[c * 4 + 1];
                s += fmaxf(uq[c * 4 + 2] - hv.z, 0.f) * w2c[c * 4 + 2];
                s += fmaxf(uq[c * 4 + 3] - hv.w, 0.f) * w2c[c * 4 + 3];
            }
            if (s > mmax) {   // rare after warmup: rescale running state
                float corr = __expf(mmax - s);
                lsum *= corr;
#pragma unroll
                for (int c = 0; c < 16; c++) {
                    acc[c].x *= corr; acc[c].y *= corr;
                    acc[c].z *= corr; acc[c].w *= corr;
                }
                mmax = s;
            }
            float p = __expf(s - mmax);
            lsum += p;
            const float4* vr = Vs + kk * 16;
#pragma unroll
            for (int c = 0; c < 16; c++) {
                float4 vv = vr[c];
                acc[c].x += p * vv.x; acc[c].y += p * vv.y;
                acc[c].z += p * vv.z; acc[c].w += p * vv.w;
            }
        }
    }

    const float inv = 1.f / lsum;
    float* orow = ctx + ((size_t)(m * NQ + q)) * INNER + h * HDD;
#pragma unroll
    for (int c = 0; c < 16; c++) {
        *(float4*)(orow + c * 4) = make_float4(acc[c].x * inv, acc[c].y * inv,
                                               acc[c].z * inv, acc[c].w * inv);
    }
}

// ---------------------------------------------------------------------------
extern "C" void kernel_launch(void* const* d_in, const int* in_sizes, int n_in,
                              void* d_out, int out_size)
{
    const float* xq    = (const float*)d_in[0];
    const float* xk    = (const float*)d_in[1];
    const float* xv    = (const float*)d_in[2];
    const float* tq    = (const float*)d_in[3];
    const float* tk    = (const float*)d_in[4];
    const float* w_q   = (const float*)d_in[5];
    const float* w_k   = (const float*)d_in[6];
    const float* w_v   = (const float*)d_in[7];
    const float* w_out = (const float*)d_in[8];
    const float* b_out = (const float*)d_in[9];
    const float* kw1   = (const float*)d_in[10];
    const float* kb1   = (const float*)d_in[11];
    const float* kw2   = (const float*)d_in[12];
    const float* kb2   = (const float*)d_in[13];
    float* out = (float*)d_out;

    float *qp, *kp, *vp, *cp;
    cudaGetSymbolAddress((void**)&qp, g_q);
    cudaGetSymbolAddress((void**)&kp, g_k);
    cudaGetSymbolAddress((void**)&vp, g_v);
    cudaGetSymbolAddress((void**)&cp, g_ctx);

    cudaFuncSetAttribute(attn_kernel,
                         cudaFuncAttributeMaxDynamicSharedMemorySize, ATTN_SMEM);

    const int Mtot = MB * NQ;                 // 8192
    dim3 gg(INNER / 128, Mtot / 128);         // (4, 64)
    sgemm128<<<gg, 256>>>(xq, w_q, nullptr, qp, Mtot, INNER, DXD);
    sgemm128<<<gg, 256>>>(xk, w_k, nullptr, kp, Mtot, INNER, DXD);
    sgemm128<<<gg, 256>>>(xv, w_v, nullptr, vp, Mtot, INNER, DXD);

    dim3 ga(NQ / BQ, HH, MB);                 // (8, 8, 8)
    attn_kernel<<<ga, BQ, ATTN_SMEM>>>(qp, kp, vp, tq, tk,
                                       kw1, kb1, kw2, kb2, cp);

    dim3 go(DXD / 128, Mtot / 128);           // (4, 64)
    sgemm128<<<go, 256>>>(cp, w_out, b_out, out, Mtot, DXD, INNER);
}

// round 5
// speedup vs baseline: 1.8038x; 1.8033x over previous
#include <cuda_runtime.h>
#include <cuda_bf16.h>
#include <cstdint>
#include <math.h>

typedef __nv_bfloat16 bf16;
typedef __nv_bfloat162 bf162;

#define MBN   8
#define NQL   1024
#define NKVL  1024
#define HH    8
#define SCALE 0.125f
#define DD    512

__device__ float g_q  [MBN*NQL*DD];
__device__ float g_k  [MBN*NKVL*DD];
__device__ float g_v  [MBN*NKVL*DD];
__device__ float g_ctx[MBN*NQL*DD];
__device__ float g_wt [4*DD*DD];

__device__ __forceinline__ void mma16816(float* c, const uint32_t* a,
                                         uint32_t b0, uint32_t b1){
    asm volatile(
      "mma.sync.aligned.m16n8k16.row.col.f32.bf16.bf16.f32 "
      "{%0,%1,%2,%3}, {%4,%5,%6,%7}, {%8,%9}, {%0,%1,%2,%3};"
      : "+f"(c[0]), "+f"(c[1]), "+f"(c[2]), "+f"(c[3])
      : "r"(a[0]), "r"(a[1]), "r"(a[2]), "r"(a[3]), "r"(b0), "r"(b1));
}
// split two floats into packed bf16x2 (hi) and bf16x2 (mid), low half = first
__device__ __forceinline__ void psplit2(float a, float b, uint32_t& h, uint32_t& m){
    bf16 ha = __float2bfloat16_rn(a), hb = __float2bfloat16_rn(b);
    bf16 ma = __float2bfloat16_rn(a - __bfloat162float(ha));
    bf16 mb = __float2bfloat16_rn(b - __bfloat162float(hb));
    bf162 H = __halves2bfloat162(ha, hb), M = __halves2bfloat162(ma, mb);
    h = *(uint32_t*)&H; m = *(uint32_t*)&M;
}

// ---------------- W[k][n] -> Wt[n][k] ----------------
__global__ void wtrans(const float* __restrict__ W, float* __restrict__ Wt){
    __shared__ float t[32][33];
    int n0 = blockIdx.x*32, k0 = blockIdx.y*32;
    int tx = threadIdx.x, ty = threadIdx.y;
#pragma unroll
    for (int i=0;i<32;i+=8) t[ty+i][tx] = W[(size_t)(k0+ty+i)*DD + n0+tx];
    __syncthreads();
#pragma unroll
    for (int i=0;i<32;i+=8) Wt[(size_t)(n0+ty+i)*DD + k0+tx] = t[tx][ty+i];
}

// ---------------- GEMM: C = scale*(A @ Bt^T) + bias ----------------
// A[8192][512] f32, Bt[512][512] f32 (n-major). 128x128 tile, 8 warps.
__global__ void __launch_bounds__(256) proj_mma(
    const float* __restrict__ A, const float* __restrict__ Bt,
    const float* __restrict__ bias, float* __restrict__ C, float scale)
{
    __shared__ bf16 Ash[128*40], Asm[128*40], Bsh[128*40], Bsm[128*40];
    const int tid = threadIdx.x, lane = tid & 31, wid = tid >> 5;
    const int ln4 = lane >> 2, q2 = (lane & 3)*2;
    const int wm = (wid & 1)*64, wn = (wid >> 1)*32;
    const int bm = blockIdx.y*128, bn = blockIdx.x*128;
    float acc[4][4][4];
#pragma unroll
    for (int a=0;a<4;a++)
#pragma unroll
      for (int b=0;b<4;b++)
#pragma unroll
        for (int c=0;c<4;c++) acc[a][b][c]=0.f;

#pragma unroll 1
    for (int kt = 0; kt < 16; kt++){
        int k0 = kt*32;
        __syncthreads();
#pragma unroll
        for (int i = tid; i < 1024; i += 256){
            int r = i>>3, c4 = (i&7)*4;
            float4 v = *(const float4*)(A + (size_t)(bm+r)*DD + k0 + c4);
            uint32_t h0,m0,h1,m1;
            psplit2(v.x,v.y,h0,m0); psplit2(v.z,v.w,h1,m1);
            *(uint32_t*)(Ash + r*40 + c4) = h0;   *(uint32_t*)(Ash + r*40 + c4+2) = h1;
            *(uint32_t*)(Asm + r*40 + c4) = m0;   *(uint32_t*)(Asm + r*40 + c4+2) = m1;
            v = *(const float4*)(Bt + (size_t)(bn+r)*DD + k0 + c4);
            psplit2(v.x,v.y,h0,m0); psplit2(v.z,v.w,h1,m1);
            *(uint32_t*)(Bsh + r*40 + c4) = h0;   *(uint32_t*)(Bsh + r*40 + c4+2) = h1;
            *(uint32_t*)(Bsm + r*40 + c4) = m0;   *(uint32_t*)(Bsm + r*40 + c4+2) = m1;
        }
        __syncthreads();
#pragma unroll
        for (int ks = 0; ks < 2; ks++){
            int kb = ks*16 + q2;
            uint32_t ah[4][4], am[4][4];
#pragma unroll
            for (int mi = 0; mi < 4; mi++){
                const bf16* p = Ash + (wm + mi*16 + ln4)*40 + kb;
                ah[mi][0]=*(const uint32_t*)p;     ah[mi][1]=*(const uint32_t*)(p+8*40);
                ah[mi][2]=*(const uint32_t*)(p+8); ah[mi][3]=*(const uint32_t*)(p+8*40+8);
                const bf16* pm = Asm + (wm + mi*16 + ln4)*40 + kb;
                am[mi][0]=*(const uint32_t*)pm;     am[mi][1]=*(const uint32_t*)(pm+8*40);
                am[mi][2]=*(const uint32_t*)(pm+8); am[mi][3]=*(const uint32_t*)(pm+8*40+8);
            }
#pragma unroll
            for (int nj = 0; nj < 4; nj++){
                const bf16* p = Bsh + (wn + nj*8 + ln4)*40 + kb;
                uint32_t bh0 = *(const uint32_t*)p, bh1 = *(const uint32_t*)(p+8);
                const bf16* pm = Bsm + (wn + nj*8 + ln4)*40 + kb;
                uint32_t bm0 = *(const uint32_t*)pm, bm1 = *(const uint32_t*)(pm+8);
#pragma unroll
                for (int mi = 0; mi < 4; mi++){
                    mma16816(acc[mi][nj], ah[mi], bh0, bh1);
                    mma16816(acc[mi][nj], ah[mi], bm0, bm1);
                    mma16816(acc[mi][nj], am[mi], bh0, bh1);
                }
            }
        }
    }
#pragma unroll
    for (int mi = 0; mi < 4; mi++){
        int r0 = bm + wm + mi*16 + ln4;
#pragma unroll
        for (int nj = 0; nj < 4; nj++){
            int c = bn + wn + nj*8 + q2;
            float b0 = bias ? bias[c] : 0.f, b1 = bias ? bias[c+1] : 0.f;
            *(float2*)(C + (size_t)r0*DD + c) =
                make_float2(acc[mi][nj][0]*scale + b0, acc[mi][nj][1]*scale + b1);
            *(float2*)(C + (size_t)(r0+8)*DD + c) =
                make_float2(acc[mi][nj][2]*scale + b0, acc[mi][nj][3]*scale + b1);
        }
    }
}

// ---------------- fused attention ----------------
#define AST 72
#define O_QH 0
#define O_QM (128*AST*2)
#define O_KH (O_QM + 128*AST*2)
#define O_KM (O_KH + 64*AST*2)
#define O_VH (O_KM + 64*AST*2)
#define O_VM (O_VH + 64*AST*2)
#define O_HK (O_VM + 64*AST*2)
#define O_V1 (O_HK + 64*20*4)
#define AT_SMEM (O_V1 + 64*4)

__global__ void __launch_bounds__(256) attn_mma(
    const float* __restrict__ Qg, const float* __restrict__ Kg,
    const float* __restrict__ Vg,
    const float* __restrict__ Tq, const float* __restrict__ Tk,
    const float* __restrict__ kw1, const float* __restrict__ kb1,
    const float* __restrict__ kw2, const float* __restrict__ kb2,
    float* __restrict__ ctx)
{
    extern __shared__ char smr[];
    bf16* Qh = (bf16*)(smr + O_QH);  bf16* Qm = (bf16*)(smr + O_QM);
    bf16* Kh = (bf16*)(smr + O_KH);  bf16* Km = (bf16*)(smr + O_KM);
    bf16* Vh = (bf16*)(smr + O_VH);  bf16* Vm = (bf16*)(smr + O_VM);
    float* HkF = (float*)(smr + O_HK);
    float* V1F = (float*)(smr + O_V1);

    const int tid = threadIdx.x, lane = tid & 31, wid = tid >> 5;
    const int ln4 = lane >> 2, q2 = (lane & 3)*2;
    const int m = blockIdx.z, h = blockIdx.y, q0 = blockIdx.x*128;
    const int rl0 = wid*16 + ln4;

    // Q tile split into smem (Q already pre-scaled by SCALE in projection)
#pragma unroll
    for (int i = tid; i < 2048; i += 256){
        int r = i>>4, c4 = (i&15)*4;
        float4 v = *(const float4*)(Qg + (size_t)(m*NQL+q0+r)*DD + h*64 + c4);
        uint32_t h0,m0,h1,m1;
        psplit2(v.x,v.y,h0,m0); psplit2(v.z,v.w,h1,m1);
        *(uint32_t*)(Qh + r*AST + c4) = h0;  *(uint32_t*)(Qh + r*AST + c4+2) = h1;
        *(uint32_t*)(Qm + r*AST + c4) = m0;  *(uint32_t*)(Qm + r*AST + c4+2) = m1;
    }

    float ws[16], uq0[16], uq1[16];
    float2 ta = *(const float2*)(Tq + (size_t)(m*NQL + q0 + rl0)*2);
    float2 tb = *(const float2*)(Tq + (size_t)(m*NQL + q0 + rl0 + 8)*2);
    float U1r0 = kb2[h] - 10.f, U1r1 = U1r0;
#pragma unroll
    for (int j = 0; j < 16; j++){
        ws[j]  = 0.5f*kw2[j*HH + h];
        float w0 = kw1[j], w1 = kw1[16+j], b = kb1[j];
        uq0[j] = ta.x*w0 + ta.y*w1 + b;
        uq1[j] = tb.x*w0 + tb.y*w1 + b;
        U1r0 = fmaf(ws[j], uq0[j], U1r0);
        U1r1 = fmaf(ws[j], uq1[j], U1r1);
    }

    float oacc[8][4];
#pragma unroll
    for (int j=0;j<8;j++)
#pragma unroll
        for (int c=0;c<4;c++) oacc[j][c]=0.f;
    float l0 = 0.f, l1 = 0.f;

#pragma unroll 1
    for (int kk0 = 0; kk0 < NKVL; kk0 += 64){
        __syncthreads();
#pragma unroll
        for (int i = tid; i < 1024; i += 256){
            int r = i>>4, c4 = (i&15)*4;
            float4 v = *(const float4*)(Kg + (size_t)(m*NKVL+kk0+r)*DD + h*64 + c4);
            uint32_t h0,m0,h1,m1;
            psplit2(v.x,v.y,h0,m0); psplit2(v.z,v.w,h1,m1);
            *(uint32_t*)(Kh + r*AST + c4) = h0;  *(uint32_t*)(Kh + r*AST + c4+2) = h1;
            *(uint32_t*)(Km + r*AST + c4) = m0;  *(uint32_t*)(Km + r*AST + c4+2) = m1;
            // V transposed: Vh[d][kk]
            v = *(const float4*)(Vg + (size_t)(m*NKVL+kk0+r)*DD + h*64 + c4);
            float vv[4] = {v.x, v.y, v.z, v.w};
#pragma unroll
            for (int e = 0; e < 4; e++){
                bf16 hh = __float2bfloat16_rn(vv[e]);
                Vh[(c4+e)*AST + r] = hh;
                Vm[(c4+e)*AST + r] = __float2bfloat16_rn(vv[e] - __bfloat162float(hh));
            }
        }
        if (tid < 64){
            float2 tk2 = *(const float2*)(Tk + (size_t)(m*NKVL + kk0 + tid)*2);
            float v1 = 0.f;
#pragma unroll
            for (int j = 0; j < 16; j++){
                float hk = tk2.x*kw1[j] + tk2.y*kw1[16+j];
                HkF[tid*20 + j] = hk;
                v1 = fmaf(0.5f*kw2[j*HH + h], hk, v1);
            }
            V1F[tid] = v1;
        }
        __syncthreads();

        float sacc[8][4];
#pragma unroll
        for (int j=0;j<8;j++)
#pragma unroll
            for (int c=0;c<4;c++) sacc[j][c]=0.f;
#pragma unroll
        for (int ks = 0; ks < 4; ks++){
            int kb = ks*16 + q2;
            uint32_t qa[4], qb[4];
            const bf16* p = Qh + rl0*AST + kb;
            qa[0]=*(const uint32_t*)p;     qa[1]=*(const uint32_t*)(p+8*AST);
            qa[2]=*(const uint32_t*)(p+8); qa[3]=*(const uint32_t*)(p+8*AST+8);
            const bf16* pm = Qm + rl0*AST + kb;
            qb[0]=*(const uint32_t*)pm;     qb[1]=*(const uint32_t*)(pm+8*AST);
            qb[2]=*(const uint32_t*)(pm+8); qb[3]=*(const uint32_t*)(pm+8*AST+8);
#pragma unroll
            for (int j = 0; j < 8; j++){
                const bf16* pk = Kh + (j*8 + ln4)*AST + kb;
                uint32_t bh0 = *(const uint32_t*)pk, bh1 = *(const uint32_t*)(pk+8);
                const bf16* pk2 = Km + (j*8 + ln4)*AST + kb;
                uint32_t bm0 = *(const uint32_t*)pk2, bm1 = *(const uint32_t*)(pk2+8);
                mma16816(sacc[j], qa, bh0, bh1);
                mma16816(sacc[j], qa, bm0, bm1);
                mma16816(sacc[j], qb, bh0, bh1);
            }
        }

        uint32_t pah[4][4], pam[4][4];
#pragma unroll
        for (int j = 0; j < 8; j++){
            float p00,p01,p10,p11;
#pragma unroll
            for (int e = 0; e < 2; e++){
                int c = j*8 + q2 + e;
                const float4* hp = (const float4*)(HkF + c*20);
                float4 f0 = hp[0], f1 = hp[1], f2 = hp[2], f3 = hp[3];
                float hv[16] = {f0.x,f0.y,f0.z,f0.w, f1.x,f1.y,f1.z,f1.w,
                                f2.x,f2.y,f2.z,f2.w, f3.x,f3.y,f3.z,f3.w};
                float v1c = V1F[c];
                float s0 = sacc[j][e]   + U1r0 - v1c;
                float s1 = sacc[j][2+e] + U1r1 - v1c;
#pragma unroll
                for (int jj = 0; jj < 16; jj++){
                    s0 = fmaf(ws[jj], fabsf(uq0[jj] - hv[jj]), s0);
                    s1 = fmaf(ws[jj], fabsf(uq1[jj] - hv[jj]), s1);
                }
                float e0 = __expf(s0), e1 = __expf(s1);
                l0 += e0; l1 += e1;
                if (e == 0){ p00 = e0; p10 = e1; } else { p01 = e0; p11 = e1; }
            }
            int t = j >> 1, base = (j & 1)*2;
            psplit2(p00, p01, pah[t][base],   pam[t][base]);
            psplit2(p10, p11, pah[t][base+1], pam[t][base+1]);
        }
#pragma unroll
        for (int t = 0; t < 4; t++){
            int kb = t*16 + q2;
#pragma unroll
            for (int j2 = 0; j2 < 8; j2++){
                const bf16* pv = Vh + (j2*8 + ln4)*AST + kb;
                uint32_t bh0 = *(const uint32_t*)pv, bh1 = *(const uint32_t*)(pv+8);
                const bf16* pv2 = Vm + (j2*8 + ln4)*AST + kb;
                uint32_t bm0 = *(const uint32_t*)pv2, bm1 = *(const uint32_t*)(pv2+8);
                mma16816(oacc[j2], pah[t], bh0, bh1);
                mma16816(oacc[j2], pah[t], bm0, bm1);
                mma16816(oacc[j2], pam[t], bh0, bh1);
            }
        }
    }

    l0 += __shfl_xor_sync(0xffffffffu, l0, 1);
    l0 += __shfl_xor_sync(0xffffffffu, l0, 2);
    l1 += __shfl_xor_sync(0xffffffffu, l1, 1);
    l1 += __shfl_xor_sync(0xffffffffu, l1, 2);
    float inv0 = 1.f/l0, inv1 = 1.f/l1;
    float* o0 = ctx + (size_t)(m*NQL + q0 + rl0)*DD + h*64;
    float* o1 = o0 + 8*DD;
#pragma unroll
    for (int j2 = 0; j2 < 8; j2++){
        int c = j2*8 + q2;
        *(float2*)(o0 + c) = make_float2(oacc[j2][0]*inv0, oacc[j2][1]*inv0);
        *(float2*)(o1 + c) = make_float2(oacc[j2][2]*inv1, oacc[j2][3]*inv1);
    }
}

// ---------------- host launcher ----------------
extern "C" void kernel_launch(void* const* d_in, const int* in_sizes, int n_in,
                              void* d_out, int out_size)
{
    const float* xq    = (const float*)d_in[0];
    const float* xk    = (const float*)d_in[1];
    const float* xv    = (const float*)d_in[2];
    const float* tq    = (const float*)d_in[3];
    const float* tk    = (const float*)d_in[4];
    const float* w_q   = (const float*)d_in[5];
    const float* w_k   = (const float*)d_in[6];
    const float* w_v   = (const float*)d_in[7];
    const float* w_out = (const float*)d_in[8];
    const float* b_out = (const float*)d_in[9];
    const float* kw1   = (const float*)d_in[10];
    const float* kb1   = (const float*)d_in[11];
    const float* kw2   = (const float*)d_in[12];
    const float* kb2   = (const float*)d_in[13];
    float* out = (float*)d_out;

    float *qp,*kp,*vp,*cp,*wt;
    cudaGetSymbolAddress((void**)&qp, g_q);
    cudaGetSymbolAddress((void**)&kp, g_k);
    cudaGetSymbolAddress((void**)&vp, g_v);
    cudaGetSymbolAddress((void**)&cp, g_ctx);
    cudaGetSymbolAddress((void**)&wt, g_wt);

    cudaFuncSetAttribute(attn_mma, cudaFuncAttributeMaxDynamicSharedMemorySize, AT_SMEM);

    dim3 tg(16,16), tb(32,8);
    wtrans<<<tg,tb>>>(w_q,   wt + 0*DD*DD);
    wtrans<<<tg,tb>>>(w_k,   wt + 1*DD*DD);
    wtrans<<<tg,tb>>>(w_v,   wt + 2*DD*DD);
    wtrans<<<tg,tb>>>(w_out, wt + 3*DD*DD);

    dim3 gg(4, 64);
    proj_mma<<<gg,256>>>(xq, wt+0*DD*DD, nullptr, qp, SCALE);
    proj_mma<<<gg,256>>>(xk, wt+1*DD*DD, nullptr, kp, 1.0f);
    proj_mma<<<gg,256>>>(xv, wt+2*DD*DD, nullptr, vp, 1.0f);

    dim3 ga(8, HH, MBN);
    attn_mma<<<ga,256,AT_SMEM>>>(qp, kp, vp, tq, tk, kw1, kb1, kw2, kb2, cp);

    proj_mma<<<gg,256>>>(cp, wt+3*DD*DD, b_out, out, 1.0f);
}

// round 6
// speedup vs baseline: 2.3615x; 1.3091x over previous
#include <cuda_runtime.h>
#include <cuda_bf16.h>
#include <cstdint>
#include <math.h>

typedef __nv_bfloat16 bf16;

#define MBN   8
#define NQL   1024
#define NKVL  1024
#define HH    8
#define SCALE 0.125f
#define DD    512
#define N4    (MBN*NQL*DD)

__device__ bf16  g_xh[3][N4], g_xm[3][N4];
__device__ bf16  g_wh[4][DD*DD], g_wm[4][DD*DD];
__device__ bf16  g_qh[N4], g_qm[N4], g_kh[N4], g_km[N4];
__device__ float g_vf[N4];
__device__ bf16  g_vth[N4], g_vtm[N4];
__device__ bf16  g_cth[N4], g_ctm[N4];

// ---------------- helpers ----------------
__device__ __forceinline__ uint32_t smem_u32(const void* p){
    uint32_t a;
    asm("{ .reg .u64 t; cvta.to.shared.u64 t, %1; cvt.u32.u64 %0, t; }":"=r"(a):"l"(p));
    return a;
}
__device__ __forceinline__ void cp16(uint32_t s, const void* g){
    asm volatile("cp.async.cg.shared.global [%0], [%1], 16;"::"r"(s),"l"(g));
}
#define CP_COMMIT() asm volatile("cp.async.commit_group;":::"memory")

__device__ __forceinline__ void mma16816(float* c, const uint32_t* a,
                                         uint32_t b0, uint32_t b1){
    asm volatile(
      "mma.sync.aligned.m16n8k16.row.col.f32.bf16.bf16.f32 "
      "{%0,%1,%2,%3}, {%4,%5,%6,%7}, {%8,%9}, {%0,%1,%2,%3};"
      : "+f"(c[0]), "+f"(c[1]), "+f"(c[2]), "+f"(c[3])
      : "r"(a[0]), "r"(a[1]), "r"(a[2]), "r"(a[3]), "r"(b0), "r"(b1));
}
__device__ __forceinline__ void psplit2(float a, float b, uint32_t& h, uint32_t& m){
    bf16 ha = __float2bfloat16_rn(a), hb = __float2bfloat16_rn(b);
    bf16 ma = __float2bfloat16_rn(a - __bfloat162float(ha));
    bf16 mb = __float2bfloat16_rn(b - __bfloat162float(hb));
    __nv_bfloat162 H = __halves2bfloat162(ha, hb), M = __halves2bfloat162(ma, mb);
    h = *(uint32_t*)&H; m = *(uint32_t*)&M;
}

// ---------------- input split: float -> bf16 hi/mid ----------------
__global__ void xsplit(const float* __restrict__ x, bf16* __restrict__ xh,
                       bf16* __restrict__ xm){
    int i = (blockIdx.x*256 + threadIdx.x)*4;
    float4 v = *(const float4*)(x + i);
    uint32_t h0,m0,h1,m1;
    psplit2(v.x,v.y,h0,m0); psplit2(v.z,v.w,h1,m1);
    *(uint32_t*)(xh+i) = h0; *(uint32_t*)(xh+i+2) = h1;
    *(uint32_t*)(xm+i) = m0; *(uint32_t*)(xm+i+2) = m1;
}

// ---------------- W[k][n] -> split Wt[n][k] ----------------
__global__ void wtrans(const float* __restrict__ W, bf16* __restrict__ Wh,
                       bf16* __restrict__ Wm){
    __shared__ float t[32][33];
    int n0 = blockIdx.x*32, k0 = blockIdx.y*32;
    int tx = threadIdx.x, ty = threadIdx.y;
#pragma unroll
    for (int i=0;i<32;i+=8) t[ty+i][tx] = W[(size_t)(k0+ty+i)*DD + n0+tx];
    __syncthreads();
#pragma unroll
    for (int i=0;i<32;i+=8){
        float v = t[tx][ty+i];
        bf16 hh = __float2bfloat16_rn(v);
        size_t idx = (size_t)(n0+ty+i)*DD + k0+tx;
        Wh[idx] = hh;
        Wm[idx] = __float2bfloat16_rn(v - __bfloat162float(hh));
    }
}

// ---------------- V[token][512] f32 -> split transposed [(m,h)*64+d][1024] ----
__global__ void vtrans(const float* __restrict__ V, bf16* __restrict__ Vh,
                       bf16* __restrict__ Vm){
    __shared__ float t[32][33];
    int z = blockIdx.z, m = z>>3, h = z&7;
    int kk0 = blockIdx.x*32, d0 = blockIdx.y*32;
    int tx = threadIdx.x, ty = threadIdx.y;
#pragma unroll
    for (int i=0;i<32;i+=8)
        t[ty+i][tx] = V[(size_t)(m*NKVL + kk0+ty+i)*DD + h*64 + d0+tx];
    __syncthreads();
#pragma unroll
    for (int i=0;i<32;i+=8){
        float v = t[tx][ty+i];
        bf16 hh = __float2bfloat16_rn(v);
        size_t idx = (size_t)(z*64 + d0+ty+i)*NKVL + kk0 + tx;
        Vh[idx] = hh;
        Vm[idx] = __float2bfloat16_rn(v - __bfloat162float(hh));
    }
}

// ---------------- GEMM: C = scale*(A @ Bt^T) + bias, pre-split bf16 ----------
// stage: Ah@0 Am@10240 Bh@20480 Bm@30720, stride 40 bf16 (80B), STG=40960
#define PSTG 40960
#define PJ_SMEM (2*PSTG)

__global__ void __launch_bounds__(256) proj_bf(
    const bf16* __restrict__ Ah, const bf16* __restrict__ Am,
    const bf16* __restrict__ Bh, const bf16* __restrict__ Bm,
    const float* __restrict__ bias, float* __restrict__ Cf,
    bf16* __restrict__ Ch, bf16* __restrict__ Cm, float scale)
{
    extern __shared__ char sp[];
    uint32_t sb = smem_u32(sp);
    const int tid = threadIdx.x, lane = tid & 31, wid = tid >> 5;
    const int ln4 = lane >> 2, q2 = (lane & 3)*2;
    const int wm = (wid & 1)*64, wn = (wid >> 1)*32;
    const int bm = blockIdx.y*128, bn = blockIdx.x*128;
    float acc[4][4][4];
#pragma unroll
    for (int a=0;a<4;a++)
#pragma unroll
      for (int b=0;b<4;b++)
#pragma unroll
        for (int c=0;c<4;c++) acc[a][b][c]=0.f;

#define PJ_ISSUE(kt, s) do{ \
    uint32_t st = sb + (s)*PSTG; int k0 = (kt)*32; \
    for (int i = tid; i < 512; i += 256){ \
        int r = i>>2, c8 = (i&3)*8; uint32_t ro = r*80 + (i&3)*16; \
        size_t ga = (size_t)(bm+r)*DD + k0 + c8; \
        cp16(st + ro,         Ah + ga); \
        cp16(st + 10240 + ro, Am + ga); \
        size_t gb = (size_t)(bn+r)*DD + k0 + c8; \
        cp16(st + 20480 + ro, Bh + gb); \
        cp16(st + 30720 + ro, Bm + gb); \
    } CP_COMMIT(); }while(0)

    PJ_ISSUE(0, 0);
#pragma unroll 1
    for (int kt = 0; kt < 16; kt++){
        if (kt < 15){
            PJ_ISSUE(kt+1, (kt+1)&1);
            asm volatile("cp.async.wait_group 1;":::"memory");
        } else {
            asm volatile("cp.async.wait_group 0;":::"memory");
        }
        __syncthreads();
        const bf16* sAh = (const bf16*)(sp + (kt&1)*PSTG);
        const bf16* sAm = sAh + 5120;   // 10240 B
        const bf16* sBh = sAm + 5120;
        const bf16* sBm = sBh + 5120;
#pragma unroll
        for (int ks = 0; ks < 2; ks++){
            int kb = ks*16 + q2;
            uint32_t ah[4][4], am[4][4];
#pragma unroll
            for (int mi = 0; mi < 4; mi++){
                const bf16* p = sAh + (wm + mi*16 + ln4)*40 + kb;
                ah[mi][0]=*(const uint32_t*)p;     ah[mi][1]=*(const uint32_t*)(p+8*40);
                ah[mi][2]=*(const uint32_t*)(p+8); ah[mi][3]=*(const uint32_t*)(p+8*40+8);
                const bf16* pm = sAm + (wm + mi*16 + ln4)*40 + kb;
                am[mi][0]=*(const uint32_t*)pm;     am[mi][1]=*(const uint32_t*)(pm+8*40);
                am[mi][2]=*(const uint32_t*)(pm+8); am[mi][3]=*(const uint32_t*)(pm+8*40+8);
            }
#pragma unroll
            for (int nj = 0; nj < 4; nj++){
                const bf16* p = sBh + (wn + nj*8 + ln4)*40 + kb;
                uint32_t bh0 = *(const uint32_t*)p, bh1 = *(const uint32_t*)(p+8);
                const bf16* pm = sBm + (wn + nj*8 + ln4)*40 + kb;
                uint32_t bm0 = *(const uint32_t*)pm, bm1 = *(const uint32_t*)(pm+8);
#pragma unroll
                for (int mi = 0; mi < 4; mi++){
                    mma16816(acc[mi][nj], ah[mi], bh0, bh1);
                    mma16816(acc[mi][nj], ah[mi], bm0, bm1);
                    mma16816(acc[mi][nj], am[mi], bh0, bh1);
                }
            }
        }
        __syncthreads();
    }
#pragma unroll
    for (int mi = 0; mi < 4; mi++){
        int r0 = bm + wm + mi*16 + ln4;
#pragma unroll
        for (int nj = 0; nj < 4; nj++){
            int c = bn + wn + nj*8 + q2;
            float b0 = bias ? bias[c] : 0.f, b1 = bias ? bias[c+1] : 0.f;
            float v0 = acc[mi][nj][0]*scale + b0, v1 = acc[mi][nj][1]*scale + b1;
            float v2 = acc[mi][nj][2]*scale + b0, v3 = acc[mi][nj][3]*scale + b1;
            if (Cf){
                *(float2*)(Cf + (size_t)r0*DD + c)     = make_float2(v0, v1);
                *(float2*)(Cf + (size_t)(r0+8)*DD + c) = make_float2(v2, v3);
            } else {
                uint32_t h, m;
                psplit2(v0, v1, h, m);
                *(uint32_t*)(Ch + (size_t)r0*DD + c) = h;
                *(uint32_t*)(Cm + (size_t)r0*DD + c) = m;
                psplit2(v2, v3, h, m);
                *(uint32_t*)(Ch + (size_t)(r0+8)*DD + c) = h;
                *(uint32_t*)(Cm + (size_t)(r0+8)*DD + c) = m;
            }
        }
    }
}

// ---------------- fused attention ----------------
// Q: 128x64 bf16 hi/mid stride 72 (144B rows). KV stage: Kh,Km,Vh,Vm 64x72.
#define O_QH 0
#define O_QM 18432
#define O_KV 36864
#define KVSTG 36864
#define S_KH 0
#define S_KM 9216
#define S_VH 18432
#define S_VM 27648
#define O_HK (O_KV + 2*KVSTG)
#define O_V1 (O_HK + 10240)
#define AT_SMEM (O_V1 + 512)

__global__ void __launch_bounds__(256) attn_bf(
    const bf16* __restrict__ Qh_g, const bf16* __restrict__ Qm_g,
    const bf16* __restrict__ Kh_g, const bf16* __restrict__ Km_g,
    const bf16* __restrict__ Vh_g, const bf16* __restrict__ Vm_g,
    const float* __restrict__ Tq, const float* __restrict__ Tk,
    const float* __restrict__ kw1, const float* __restrict__ kb1,
    const float* __restrict__ kw2, const float* __restrict__ kb2,
    bf16* __restrict__ Cth, bf16* __restrict__ Ctm)
{
    extern __shared__ char sp[];
    uint32_t sb = smem_u32(sp);
    float* HkF = (float*)(sp + O_HK);   // 2 x 64 x 20
    float* V1F = (float*)(sp + O_V1);   // 2 x 64

    const int tid = threadIdx.x, lane = tid & 31, wid = tid >> 5;
    const int ln4 = lane >> 2, q2 = (lane & 3)*2;
    const int m = blockIdx.z, h = blockIdx.y, q0 = blockIdx.x*128;
    const int rl0 = wid*16 + ln4;

    // prologue: Q tiles + KV tile 0 in one cp.async group
    for (int i = tid; i < 1024; i += 256){
        int r = i>>3; uint32_t ro = r*144 + (i&7)*16;
        size_t g = (size_t)(m*NQL+q0+r)*DD + h*64 + (i&7)*8;
        cp16(sb + O_QH + ro, Qh_g + g);
        cp16(sb + O_QM + ro, Qm_g + g);
    }
#define KV_ISSUE(kk0, s) do{ \
    uint32_t st = sb + O_KV + (s)*KVSTG; \
    for (int i = tid; i < 512; i += 256){ \
        int r = i>>3; uint32_t ro = r*144 + (i&7)*16; int c8 = (i&7)*8; \
        size_t gk = (size_t)(m*NKVL + (kk0) + r)*DD + h*64 + c8; \
        cp16(st + S_KH + ro, Kh_g + gk); \
        cp16(st + S_KM + ro, Km_g + gk); \
        size_t gv = (size_t)((m*HH+h)*64 + r)*NKVL + (kk0) + c8; \
        cp16(st + S_VH + ro, Vh_g + gv); \
        cp16(st + S_VM + ro, Vm_g + gv); \
    } CP_COMMIT(); }while(0)

    KV_ISSUE(0, 0);

    float ws[16], uq0[16], uq1[16];
    float2 ta = *(const float2*)(Tq + (size_t)(m*NQL + q0 + rl0)*2);
    float2 tb = *(const float2*)(Tq + (size_t)(m*NQL + q0 + rl0 + 8)*2);
    float U1r0 = kb2[h] - 10.f, U1r1 = U1r0;
#pragma unroll
    for (int j = 0; j < 16; j++){
        ws[j]  = 0.5f*kw2[j*HH + h];
        float w0 = kw1[j], w1 = kw1[16+j], b = kb1[j];
        uq0[j] = ta.x*w0 + ta.y*w1 + b;
        uq1[j] = tb.x*w0 + tb.y*w1 + b;
        U1r0 = fmaf(ws[j], uq0[j], U1r0);
        U1r1 = fmaf(ws[j], uq1[j], U1r1);
    }
    if (tid < 64){  // Hk for tile 0
        float2 tk2 = *(const float2*)(Tk + (size_t)(m*NKVL + tid)*2);
        float v1 = 0.f;
#pragma unroll
        for (int j = 0; j < 16; j++){
            float hk = tk2.x*kw1[j] + tk2.y*kw1[16+j];
            HkF[tid*20 + j] = hk;
            v1 = fmaf(ws[j], hk, v1);
        }
        V1F[tid] = v1;
    }

    float oacc[8][4];
#pragma unroll
    for (int j=0;j<8;j++)
#pragma unroll
        for (int c=0;c<4;c++) oacc[j][c]=0.f;
    float l0 = 0.f, l1 = 0.f;

#pragma unroll 1
    for (int t = 0; t < 16; t++){
        if (t < 15){
            KV_ISSUE((t+1)*64, (t+1)&1);
            if (tid < 64){
                float2 tk2 = *(const float2*)(Tk + (size_t)(m*NKVL + (t+1)*64 + tid)*2);
                float v1 = 0.f;
                float* Hb = HkF + ((t+1)&1)*1280;
#pragma unroll
                for (int j = 0; j < 16; j++){
                    float hk = tk2.x*kw1[j] + tk2.y*kw1[16+j];
                    Hb[tid*20 + j] = hk;
                    v1 = fmaf(ws[j], hk, v1);
                }
                V1F[((t+1)&1)*64 + tid] = v1;
            }
            asm volatile("cp.async.wait_group 1;":::"memory");
        } else {
            asm volatile("cp.async.wait_group 0;":::"memory");
        }
        __syncthreads();

        const bf16* Qh = (const bf16*)(sp + O_QH);
        const bf16* Qm = (const bf16*)(sp + O_QM);
        const char* st = sp + O_KV + (t&1)*KVSTG;
        const bf16* Kh = (const bf16*)(st + S_KH);
        const bf16* Km = (const bf16*)(st + S_KM);
        const bf16* Vh = (const bf16*)(st + S_VH);
        const bf16* Vm = (const bf16*)(st + S_VM);
        const float* Hc = HkF + (t&1)*1280;
        const float* Vc = V1F + (t&1)*64;

        float sacc[8][4];
#pragma unroll
        for (int j=0;j<8;j++)
#pragma unroll
            for (int c=0;c<4;c++) sacc[j][c]=0.f;
#pragma unroll
        for (int ks = 0; ks < 4; ks++){
            int kb = ks*16 + q2;
            uint32_t qa[4], qb[4];
            const bf16* p = Qh + rl0*72 + kb;
            qa[0]=*(const uint32_t*)p;     qa[1]=*(const uint32_t*)(p+8*72);
            qa[2]=*(const uint32_t*)(p+8); qa[3]=*(const uint32_t*)(p+8*72+8);
            const bf16* pm = Qm + rl0*72 + kb;
            qb[0]=*(const uint32_t*)pm;     qb[1]=*(const uint32_t*)(pm+8*72);
            qb[2]=*(const uint32_t*)(pm+8); qb[3]=*(const uint32_t*)(pm+8*72+8);
#pragma unroll
            for (int j = 0; j < 8; j++){
                const bf16* pk = Kh + (j*8 + ln4)*72 + kb;
                uint32_t bh0 = *(const uint32_t*)pk, bh1 = *(const uint32_t*)(pk+8);
                const bf16* pk2 = Km + (j*8 + ln4)*72 + kb;
                uint32_t bm0 = *(const uint32_t*)pk2, bm1 = *(const uint32_t*)(pk2+8);
                mma16816(sacc[j], qa, bh0, bh1);
                mma16816(sacc[j], qa, bm0, bm1);
                mma16816(sacc[j], qb, bh0, bh1);
            }
        }

        uint32_t pah[4][4], pam[4][4];
#pragma unroll
        for (int j = 0; j < 8; j++){
            float p00,p01,p10,p11;
#pragma unroll
            for (int e = 0; e < 2; e++){
                int c = j*8 + q2 + e;
                const float4* hp = (const float4*)(Hc + c*20);
                float4 f0 = hp[0], f1 = hp[1], f2 = hp[2], f3 = hp[3];
                float hv[16] = {f0.x,f0.y,f0.z,f0.w, f1.x,f1.y,f1.z,f1.w,
                                f2.x,f2.y,f2.z,f2.w, f3.x,f3.y,f3.z,f3.w};
                float v1c = Vc[c];
                float s0 = sacc[j][e]   + U1r0 - v1c;
                float s1 = sacc[j][2+e] + U1r1 - v1c;
#pragma unroll
                for (int jj = 0; jj < 16; jj++){
                    s0 = fmaf(ws[jj], fabsf(uq0[jj] - hv[jj]), s0);
                    s1 = fmaf(ws[jj], fabsf(uq1[jj] - hv[jj]), s1);
                }
                float e0 = __expf(s0), e1 = __expf(s1);
                l0 += e0; l1 += e1;
                if (e == 0){ p00 = e0; p10 = e1; } else { p01 = e0; p11 = e1; }
            }
            int tt = j >> 1, base = (j & 1)*2;
            psplit2(p00, p01, pah[tt][base],   pam[tt][base]);
            psplit2(p10, p11, pah[tt][base+1], pam[tt][base+1]);
        }
#pragma unroll
        for (int tt = 0; tt < 4; tt++){
            int kb = tt*16 + q2;
#pragma unroll
            for (int j2 = 0; j2 < 8; j2++){
                const bf16* pv = Vh + (j2*8 + ln4)*72 + kb;
                uint32_t bh0 = *(const uint32_t*)pv, bh1 = *(const uint32_t*)(pv+8);
                const bf16* pv2 = Vm + (j2*8 + ln4)*72 + kb;
                uint32_t bm0 = *(const uint32_t*)pv2, bm1 = *(const uint32_t*)(pv2+8);
                mma16816(oacc[j2], pah[tt], bh0, bh1);
                mma16816(oacc[j2], pah[tt], bm0, bm1);
                mma16816(oacc[j2], pam[tt], bh0, bh1);
            }
        }
        __syncthreads();
    }

    l0 += __shfl_xor_sync(0xffffffffu, l0, 1);
    l0 += __shfl_xor_sync(0xffffffffu, l0, 2);
    l1 += __shfl_xor_sync(0xffffffffu, l1, 1);
    l1 += __shfl_xor_sync(0xffffffffu, l1, 2);
    float inv0 = 1.f/l0, inv1 = 1.f/l1;
    size_t o0 = (size_t)(m*NQL + q0 + rl0)*DD + h*64;
    size_t o1 = o0 + 8*DD;
#pragma unroll
    for (int j2 = 0; j2 < 8; j2++){
        int c = j2*8 + q2;
        uint32_t hh, mm;
        psplit2(oacc[j2][0]*inv0, oacc[j2][1]*inv0, hh, mm);
        *(uint32_t*)(Cth + o0 + c) = hh; *(uint32_t*)(Ctm + o0 + c) = mm;
        psplit2(oacc[j2][2]*inv1, oacc[j2][3]*inv1, hh, mm);
        *(uint32_t*)(Cth + o1 + c) = hh; *(uint32_t*)(Ctm + o1 + c) = mm;
    }
}

// ---------------- host launcher ----------------
extern "C" void kernel_launch(void* const* d_in, const int* in_sizes, int n_in,
                              void* d_out, int out_size)
{
    const float* xq    = (const float*)d_in[0];
    const float* xk    = (const float*)d_in[1];
    const float* xv    = (const float*)d_in[2];
    const float* tq    = (const float*)d_in[3];
    const float* tk    = (const float*)d_in[4];
    const float* w_q   = (const float*)d_in[5];
    const float* w_k   = (const float*)d_in[6];
    const float* w_v   = (const float*)d_in[7];
    const float* w_out = (const float*)d_in[8];
    const float* b_out = (const float*)d_in[9];
    const float* kw1   = (const float*)d_in[10];
    const float* kb1   = (const float*)d_in[11];
    const float* kw2   = (const float*)d_in[12];
    const float* kb2   = (const float*)d_in[13];
    float* out = (float*)d_out;

    bf16 *xh,*xm,*wh,*wm,*qh,*qm,*kh,*km,*vth,*vtm,*cth,*ctm;
    float *vf;
    cudaGetSymbolAddress((void**)&xh,  g_xh);
    cudaGetSymbolAddress((void**)&xm,  g_xm);
    cudaGetSymbolAddress((void**)&wh,  g_wh);
    cudaGetSymbolAddress((void**)&wm,  g_wm);
    cudaGetSymbolAddress((void**)&qh,  g_qh);
    cudaGetSymbolAddress((void**)&qm,  g_qm);
    cudaGetSymbolAddress((void**)&kh,  g_kh);
    cudaGetSymbolAddress((void**)&km,  g_km);
    cudaGetSymbolAddress((void**)&vf,  g_vf);
    cudaGetSymbolAddress((void**)&vth, g_vth);
    cudaGetSymbolAddress((void**)&vtm, g_vtm);
    cudaGetSymbolAddress((void**)&cth, g_cth);
    cudaGetSymbolAddress((void**)&ctm, g_ctm);

    cudaFuncSetAttribute(proj_bf, cudaFuncAttributeMaxDynamicSharedMemorySize, PJ_SMEM);
    cudaFuncSetAttribute(attn_bf, cudaFuncAttributeMaxDynamicSharedMemorySize, AT_SMEM);

    xsplit<<<N4/1024, 256>>>(xq, xh + 0*(size_t)N4, xm + 0*(size_t)N4);
    xsplit<<<N4/1024, 256>>>(xk, xh + 1*(size_t)N4, xm + 1*(size_t)N4);
    xsplit<<<N4/1024, 256>>>(xv, xh + 2*(size_t)N4, xm + 2*(size_t)N4);

    dim3 tg(16,16), tb(32,8);
    wtrans<<<tg,tb>>>(w_q,   wh + 0*DD*DD, wm + 0*DD*DD);
    wtrans<<<tg,tb>>>(w_k,   wh + 1*DD*DD, wm + 1*DD*DD);
    wtrans<<<tg,tb>>>(w_v,   wh + 2*DD*DD, wm + 2*DD*DD);
    wtrans<<<tg,tb>>>(w_out, wh + 3*DD*DD, wm + 3*DD*DD);

    dim3 gg(4, 64);
    proj_bf<<<gg,256,PJ_SMEM>>>(xh+0*(size_t)N4, xm+0*(size_t)N4,
                                wh+0*DD*DD, wm+0*DD*DD,
                                nullptr, nullptr, qh, qm, SCALE);
    proj_bf<<<gg,256,PJ_SMEM>>>(xh+1*(size_t)N4, xm+1*(size_t)N4,
                                wh+1*DD*DD, wm+1*DD*DD,
                                nullptr, nullptr, kh, km, 1.0f);
    proj_bf<<<gg,256,PJ_SMEM>>>(xh+2*(size_t)N4, xm+2*(size_t)N4,
                                wh+2*DD*DD, wm+2*DD*DD,
                                nullptr, vf, nullptr, nullptr, 1.0f);

    dim3 gv(32, 2, 64);
    vtrans<<<gv,tb>>>(vf, vth, vtm);

    dim3 ga(8, HH, MBN);
    attn_bf<<<ga,256,AT_SMEM>>>(qh, qm, kh, km, vth, vtm,
                                tq, tk, kw1, kb1, kw2, kb2, cth, ctm);

    proj_bf<<<gg,256,PJ_SMEM>>>(cth, ctm, wh+3*DD*DD, wm+3*DD*DD,
                                b_out, out, nullptr, nullptr, 1.0f);
}